// round 1
// baseline (speedup 1.0000x reference)
#include <cuda_runtime.h>
#include <math.h>

#define BB 8
#define CC 256
#define CI 128
#define HH 64
#define WD 64
#define NPIX 4096   // 64*64
#define NPOOL 1024  // 32*32
#define BN_EPS 1e-5f

// ---------------- scratch (single __device__ global, no allocations) ----------
#define SZ_PROJ ((size_t)BB * CI * NPIX)    // 4,194,304 floats
#define SZ_POOL ((size_t)BB * CI * NPOOL)   // 1,048,576
#define SZ_F    ((size_t)BB * NPIX * NPOOL) // 33,554,432

#define OFF_THETA ((size_t)0)              // [b][ci][n]
#define OFF_PHIF  (SZ_PROJ)                // [b][ci][n] full-res phi conv
#define OFF_GF    (2 * SZ_PROJ)            // [b][ci][n] full-res g conv
#define OFF_PHIP  (3 * SZ_PROJ)            // [b][ci][m] pooled phi
#define OFF_GPT   (OFF_PHIP + SZ_POOL)     // [b][m][ci] pooled g (transposed)
#define OFF_F     (OFF_GPT + SZ_POOL)      // [b][n][m]
#define OFF_Y     (OFF_F + SZ_F)           // [b][n][ci]
#define SCRATCH_SZ (OFF_Y + SZ_PROJ)       // 52,428,800 floats (~210 MB)

__device__ float d_scratch[SCRATCH_SZ];

// ---------------- shared 64x64x16 fp32 micro-kernel ---------------------------
__device__ __forceinline__ void mm16(const float (*As)[68], const float (*Bs)[68],
                                     float acc[4][4], int tx, int ty)
{
#pragma unroll
    for (int k = 0; k < 16; ++k) {
        float4 a = *(const float4*)&As[k][ty << 2];
        float4 v = *(const float4*)&Bs[k][tx << 2];
        acc[0][0] += a.x * v.x; acc[0][1] += a.x * v.y; acc[0][2] += a.x * v.z; acc[0][3] += a.x * v.w;
        acc[1][0] += a.y * v.x; acc[1][1] += a.y * v.y; acc[1][2] += a.y * v.z; acc[1][3] += a.y * v.w;
        acc[2][0] += a.z * v.x; acc[2][1] += a.z * v.y; acc[2][2] += a.z * v.z; acc[2][3] += a.z * v.w;
        acc[3][0] += a.w * v.x; acc[3][1] += a.w * v.y; acc[3][2] += a.w * v.z; acc[3][3] += a.w * v.w;
    }
}

// ---------------- 1) projection GEMM: out[b][m][n] = sum_k w[m][k]*x[b][k][n] + bias[m]
// M=CI, N=NPIX, K=CC. grid (NPIX/64, CI/64, BB), block 256.
__global__ __launch_bounds__(256) void proj_kernel(
    const float* __restrict__ x, const float* __restrict__ w,
    const float* __restrict__ bias, int sel)
{
    float* out = d_scratch + (size_t)sel * SZ_PROJ;
    const int b  = blockIdx.z;
    const int n0 = blockIdx.x * 64;
    const int m0 = blockIdx.y * 64;
    const float* X = x + (size_t)b * CC * NPIX;
    float* O = out + (size_t)b * CI * NPIX;

    __shared__ float As[16][68];
    __shared__ float Bs[16][68];

    const int tid = threadIdx.x;
    const int tx = tid & 15, ty = tid >> 4;
    const int am = tid >> 2, ak = (tid & 3) << 2;   // A transpose-loader
    const int bk = tid >> 4, bn = (tid & 15) << 2;  // B direct loader

    float acc[4][4] = {};
    for (int k0 = 0; k0 < CC; k0 += 16) {
        float4 av = *(const float4*)(w + (size_t)(m0 + am) * CC + k0 + ak);
        As[ak + 0][am] = av.x; As[ak + 1][am] = av.y;
        As[ak + 2][am] = av.z; As[ak + 3][am] = av.w;
        *(float4*)&Bs[bk][bn] = *(const float4*)(X + (size_t)(k0 + bk) * NPIX + n0 + bn);
        __syncthreads();
        mm16(As, Bs, acc, tx, ty);
        __syncthreads();
    }
#pragma unroll
    for (int i = 0; i < 4; ++i) {
        int m = m0 + (ty << 2) + i;
        float bv = bias[m];
        float4 r = make_float4(acc[i][0] + bv, acc[i][1] + bv, acc[i][2] + bv, acc[i][3] + bv);
        *(float4*)(O + (size_t)m * NPIX + n0 + (tx << 2)) = r;
    }
}

// ---------------- 2) 2x2 max pool: phiP[b][ci][m], gPt[b][m][ci] ---------------
__global__ __launch_bounds__(256) void pool_kernel()
{
    int idx = blockIdx.x * blockDim.x + threadIdx.x;   // (b,ci,m), m fastest
    if (idx >= (int)(BB * CI * NPOOL)) return;
    int m  = idx & (NPOOL - 1);
    int ci = (idx >> 10) & (CI - 1);
    int b  = idx >> 17;
    int ph = m >> 5, pw = m & 31;
    size_t base = ((size_t)b * CI + ci) * NPIX + (size_t)(2 * ph) * WD + 2 * pw;

    const float* pf = d_scratch + OFF_PHIF;
    float p = fmaxf(fmaxf(pf[base], pf[base + 1]),
                    fmaxf(pf[base + WD], pf[base + WD + 1]));
    d_scratch[OFF_PHIP + (size_t)idx] = p;

    const float* gf = d_scratch + OFF_GF;
    float g = fmaxf(fmaxf(gf[base], gf[base + 1]),
                    fmaxf(gf[base + WD], gf[base + WD + 1]));
    d_scratch[OFF_GPT + ((size_t)b * NPOOL + m) * CI + ci] = g;
}

// ---------------- 3) f GEMM (TN): f[b][n][m] = sum_k theta[b][k][n]*phiP[b][k][m]
// M=NPIX(n), N=NPOOL(m), K=CI. grid (NPOOL/64, NPIX/64, BB)
__global__ __launch_bounds__(256) void gemm_f_kernel()
{
    const int b  = blockIdx.z;
    const int c0 = blockIdx.x * 64;
    const int r0 = blockIdx.y * 64;
    const float* A = d_scratch + OFF_THETA + (size_t)b * CI * NPIX;
    const float* Bm = d_scratch + OFF_PHIP + (size_t)b * CI * NPOOL;
    float* F = d_scratch + OFF_F + (size_t)b * NPIX * NPOOL;

    __shared__ float As[16][68];
    __shared__ float Bs[16][68];
    const int tid = threadIdx.x;
    const int tx = tid & 15, ty = tid >> 4;
    const int lk = tid >> 4, lc = (tid & 15) << 2;

    float acc[4][4] = {};
    for (int k0 = 0; k0 < CI; k0 += 16) {
        *(float4*)&As[lk][lc] = *(const float4*)(A  + (size_t)(k0 + lk) * NPIX  + r0 + lc);
        *(float4*)&Bs[lk][lc] = *(const float4*)(Bm + (size_t)(k0 + lk) * NPOOL + c0 + lc);
        __syncthreads();
        mm16(As, Bs, acc, tx, ty);
        __syncthreads();
    }
#pragma unroll
    for (int i = 0; i < 4; ++i) {
        *(float4*)(F + (size_t)(r0 + (ty << 2) + i) * NPOOL + c0 + (tx << 2)) =
            make_float4(acc[i][0], acc[i][1], acc[i][2], acc[i][3]);
    }
}

// ---------------- 4) row softmax over m (1024), block per row -----------------
__global__ __launch_bounds__(256) void softmax_kernel()
{
    __shared__ float rmax[8], rsum[8], bval[2];
    size_t row = blockIdx.x;
    float4* p = (float4*)(d_scratch + OFF_F + row * (size_t)NPOOL);
    const int tid = threadIdx.x;
    const int lane = tid & 31, wid = tid >> 5;

    float4 v = p[tid];
    float mx = fmaxf(fmaxf(v.x, v.y), fmaxf(v.z, v.w));
#pragma unroll
    for (int o = 16; o; o >>= 1) mx = fmaxf(mx, __shfl_xor_sync(0xffffffffu, mx, o));
    if (lane == 0) rmax[wid] = mx;
    __syncthreads();
    if (tid == 0) {
        float m = rmax[0];
#pragma unroll
        for (int i = 1; i < 8; ++i) m = fmaxf(m, rmax[i]);
        bval[0] = m;
    }
    __syncthreads();
    float M = bval[0];
    v.x = expf(v.x - M); v.y = expf(v.y - M);
    v.z = expf(v.z - M); v.w = expf(v.w - M);
    float s = v.x + v.y + v.z + v.w;
#pragma unroll
    for (int o = 16; o; o >>= 1) s += __shfl_xor_sync(0xffffffffu, s, o);
    if (lane == 0) rsum[wid] = s;
    __syncthreads();
    if (tid == 0) {
        float t = 0.f;
#pragma unroll
        for (int i = 0; i < 8; ++i) t += rsum[i];
        bval[1] = 1.f / t;
    }
    __syncthreads();
    float r = bval[1];
    v.x *= r; v.y *= r; v.z *= r; v.w *= r;
    p[tid] = v;
}

// ---------------- 5) y GEMM (NN): y[b][n][c] = sum_k f[b][n][k]*gPt[b][k][c]
// M=NPIX, N=CI, K=NPOOL. grid (CI/64, NPIX/64, BB)
__global__ __launch_bounds__(256) void gemm_y_kernel()
{
    const int b  = blockIdx.z;
    const int c0 = blockIdx.x * 64;
    const int r0 = blockIdx.y * 64;
    const float* F = d_scratch + OFF_F   + (size_t)b * NPIX * NPOOL;
    const float* G = d_scratch + OFF_GPT + (size_t)b * NPOOL * CI;
    float* Y = d_scratch + OFF_Y + (size_t)b * NPIX * CI;

    __shared__ float As[16][68];
    __shared__ float Bs[16][68];
    const int tid = threadIdx.x;
    const int tx = tid & 15, ty = tid >> 4;
    const int am = tid >> 2, ak = (tid & 3) << 2;
    const int bk = tid >> 4, bn = (tid & 15) << 2;

    float acc[4][4] = {};
    for (int k0 = 0; k0 < NPOOL; k0 += 16) {
        float4 av = *(const float4*)(F + (size_t)(r0 + am) * NPOOL + k0 + ak);
        As[ak + 0][am] = av.x; As[ak + 1][am] = av.y;
        As[ak + 2][am] = av.z; As[ak + 3][am] = av.w;
        *(float4*)&Bs[bk][bn] = *(const float4*)(G + (size_t)(k0 + bk) * CI + c0 + bn);
        __syncthreads();
        mm16(As, Bs, acc, tx, ty);
        __syncthreads();
    }
#pragma unroll
    for (int i = 0; i < 4; ++i) {
        *(float4*)(Y + (size_t)(r0 + (ty << 2) + i) * CI + c0 + (tx << 2)) =
            make_float4(acc[i][0], acc[i][1], acc[i][2], acc[i][3]);
    }
}

// ---------------- 6) out GEMM + BN + residual ---------------------------------
// o[b][c][n] = ((sum_k Ww[c][k]*y[b][n][k]) + Wb[c] - mean[c])*inv[c] + beta[c] + x[b][c][n]
// M=CC(c), N=NPIX(n), K=CI. grid (NPIX/64, CC/64, BB)
__global__ __launch_bounds__(256) void gemm_out_kernel(
    const float* __restrict__ Ww, const float* __restrict__ Wb,
    const float* __restrict__ gamma, const float* __restrict__ beta,
    const float* __restrict__ mean, const float* __restrict__ var,
    const float* __restrict__ x, float* __restrict__ out)
{
    const int b  = blockIdx.z;
    const int n0 = blockIdx.x * 64;
    const int m0 = blockIdx.y * 64;
    const float* Y = d_scratch + OFF_Y + (size_t)b * NPIX * CI;

    __shared__ float As[16][68];
    __shared__ float Bs[16][68];
    const int tid = threadIdx.x;
    const int tx = tid & 15, ty = tid >> 4;
    const int am = tid >> 2, ak = (tid & 3) << 2;  // reused for both transpose loaders

    float acc[4][4] = {};
    for (int k0 = 0; k0 < CI; k0 += 16) {
        float4 av = *(const float4*)(Ww + (size_t)(m0 + am) * CI + k0 + ak);
        As[ak + 0][am] = av.x; As[ak + 1][am] = av.y;
        As[ak + 2][am] = av.z; As[ak + 3][am] = av.w;
        float4 bv = *(const float4*)(Y + (size_t)(n0 + am) * CI + k0 + ak);
        Bs[ak + 0][am] = bv.x; Bs[ak + 1][am] = bv.y;
        Bs[ak + 2][am] = bv.z; Bs[ak + 3][am] = bv.w;
        __syncthreads();
        mm16(As, Bs, acc, tx, ty);
        __syncthreads();
    }
#pragma unroll
    for (int i = 0; i < 4; ++i) {
        int c = m0 + (ty << 2) + i;
        float inv = gamma[c] / sqrtf(var[c] + BN_EPS);
        float sh = (Wb[c] - mean[c]) * inv + beta[c];
        size_t off = ((size_t)b * CC + c) * NPIX + n0 + (tx << 2);
        float4 xv = *(const float4*)(x + off);
        float4 r = make_float4(acc[i][0] * inv + sh + xv.x,
                               acc[i][1] * inv + sh + xv.y,
                               acc[i][2] * inv + sh + xv.z,
                               acc[i][3] * inv + sh + xv.w);
        *(float4*)(out + off) = r;
    }
}

// ---------------- launch -------------------------------------------------------
extern "C" void kernel_launch(void* const* d_in, const int* in_sizes, int n_in,
                              void* d_out, int out_size)
{
    const float* x    = (const float*)d_in[0];
    const float* g_w  = (const float*)d_in[1];
    const float* g_b  = (const float*)d_in[2];
    const float* th_w = (const float*)d_in[3];
    const float* th_b = (const float*)d_in[4];
    const float* ph_w = (const float*)d_in[5];
    const float* ph_b = (const float*)d_in[6];
    const float* W_w  = (const float*)d_in[7];
    const float* W_b  = (const float*)d_in[8];
    const float* gam  = (const float*)d_in[9];
    const float* bet  = (const float*)d_in[10];
    const float* mea  = (const float*)d_in[11];
    const float* var  = (const float*)d_in[12];
    float* out = (float*)d_out;

    dim3 blk(256);
    proj_kernel<<<dim3(NPIX / 64, CI / 64, BB), blk>>>(x, th_w, th_b, 0); // theta
    proj_kernel<<<dim3(NPIX / 64, CI / 64, BB), blk>>>(x, ph_w, ph_b, 1); // phi (full)
    proj_kernel<<<dim3(NPIX / 64, CI / 64, BB), blk>>>(x, g_w,  g_b,  2); // g (full)
    pool_kernel<<<(BB * CI * NPOOL) / 256, blk>>>();
    gemm_f_kernel<<<dim3(NPOOL / 64, NPIX / 64, BB), blk>>>();
    softmax_kernel<<<BB * NPIX, blk>>>();
    gemm_y_kernel<<<dim3(CI / 64, NPIX / 64, BB), blk>>>();
    gemm_out_kernel<<<dim3(NPIX / 64, CC / 64, BB), blk>>>(W_w, W_b, gam, bet, mea, var, x, out);
}